// round 1
// baseline (speedup 1.0000x reference)
#include <cuda_runtime.h>

#define NB 16
#define H 768
#define W 768
#define HS 48
#define WS 48
#define NPIX (HS * WS)   // 2304

// scratch feats, padded to float4: [B][N] (w unused)
__device__ float4 g_feats[NB * NPIX];

__global__ void feats_kernel(const float* __restrict__ img) {
    int idx = blockIdx.x * blockDim.x + threadIdx.x;
    if (idx >= NB * NPIX) return;
    int b = idx / NPIX;
    int p = idx % NPIX;
    int yi = p / WS, xi = p % WS;
    // half-pixel centers, scale 16: in-coord = 16*i + 7.5 -> 0.25 * 2x2 quad
    int r0 = yi * 16 + 7;
    int c0 = xi * 16 + 7;
    float v[3];
#pragma unroll
    for (int c = 0; c < 3; c++) {
        const float* base = img + ((size_t)(b * 3 + c)) * H * W;
        float a = base[(size_t)r0 * W + c0] + base[(size_t)r0 * W + c0 + 1] +
                  base[(size_t)(r0 + 1) * W + c0] + base[(size_t)(r0 + 1) * W + c0 + 1];
        v[c] = 0.25f * a;
    }
    g_feats[idx] = make_float4(v[0], v[1], v[2], 0.0f);
}

// one CTA per output row (b,i); 576 threads, one float4 (4 cols) each.
__global__ __launch_bounds__(576) void affinity_kernel(float4* __restrict__ out) {
    int row = blockIdx.x;           // 0 .. NB*NPIX-1
    int b = row / NPIX;
    int i = row % NPIX;
    int yi = i / WS, xi = i % WS;

    int t = threadIdx.x;            // 0..575
    int yj = t / 12;                // 12 float4 per grid row (48/4)
    int xj0 = (t % 12) * 4;
    int dy = yi - yj;

    float4 o = make_float4(0.f, 0.f, 0.f, 0.f);
    if (dy >= -8 && dy <= 8) {
        float4 fi = g_feats[b * NPIX + i];           // uniform per CTA -> broadcast
        float sy = (float)(dy * dy);
        const float4* frow = g_feats + b * NPIX + yj * WS;
        float res[4];
#pragma unroll
        for (int k = 0; k < 4; k++) {
            int xj = xj0 + k;
            int dx = xi - xj;
            float val = 0.0f;
            if (dx >= -8 && dx <= 8) {
                float4 fj = frow[xj];
                float d0 = fi.x - fj.x;
                float d1 = fi.y - fj.y;
                float d2c = fi.z - fj.z;
                float d2 = d0 * d0 + d1 * d1 + d2c * d2c;
                float fdx = (float)dx;
                // exp(-(dy^2+dx^2)/(2*5^2)) * exp(-d2/(2*0.1^2))
                float E = fmaf(sy + fdx * fdx, -0.02f, -50.0f * d2);
                val = __expf(E);
            }
            res[k] = val;
        }
        o = make_float4(res[0], res[1], res[2], res[3]);
    }
    out[(size_t)row * (NPIX / 4) + t] = o;
}

extern "C" void kernel_launch(void* const* d_in, const int* in_sizes, int n_in,
                              void* d_out, int out_size) {
    const float* img = (const float*)d_in[0];
    feats_kernel<<<(NB * NPIX + 255) / 256, 256>>>(img);
    affinity_kernel<<<NB * NPIX, 576>>>((float4*)d_out);
}

// round 2
// speedup vs baseline: 1.1996x; 1.1996x over previous
#include <cuda_runtime.h>

#define NB 16
#define H 768
#define W 768
#define HS 48
#define WS 48
#define NPIX (HS * WS)   // 2304
#define ROWQ (NPIX / 4)  // 576 float4 per output row

// scratch feats, padded to float4: [B][N] (w unused)
__device__ float4 g_feats[NB * NPIX];

__global__ void feats_kernel(const float* __restrict__ img) {
    int idx = blockIdx.x * blockDim.x + threadIdx.x;
    if (idx >= NB * NPIX) return;
    int b = idx / NPIX;
    int p = idx % NPIX;
    int yi = p / WS, xi = p % WS;
    // half-pixel centers, scale 16: src coord = 16*i + 7.5 -> 0.25 * (2x2 quad)
    int r0 = yi * 16 + 7;
    int c0 = xi * 16 + 7;
    float v[3];
#pragma unroll
    for (int c = 0; c < 3; c++) {
        const float* base = img + ((size_t)(b * 3 + c)) * H * W;
        float a = base[(size_t)r0 * W + c0] + base[(size_t)r0 * W + c0 + 1] +
                  base[(size_t)(r0 + 1) * W + c0] + base[(size_t)(r0 + 1) * W + c0 + 1];
        v[c] = 0.25f * a;
    }
    g_feats[idx] = make_float4(v[0], v[1], v[2], 0.0f);
}

// grid: (12, 48, 16) = (xi_group, yi, b). block: (12, 48) = (xj_group, yj).
// Each thread writes one float4 (cols xj0..xj0+3) for 4 consecutive output
// rows i = yi*48 + xi0 .. +3. No integer div/mod anywhere.
__global__ __launch_bounds__(576, 2) void affinity_kernel(float4* __restrict__ out) {
    const int xi0 = blockIdx.x << 2;     // 0,4,...,44
    const int yi  = blockIdx.y;
    const int b   = blockIdx.z;
    const int xj0 = threadIdx.x << 2;    // 0,4,...,44
    const int yj  = threadIdx.y;
    const int dy  = yi - yj;

    // output float4 index for row i0 = (b*NPIX + yi*WS + xi0), col group
    float4* p = out + ((size_t)((b * HS + yi) * WS + xi0)) * ROWQ
                    + (yj * 12 + threadIdx.x);

    // x-window test: any (xi in [xi0,xi0+3], xj in [xj0,xj0+3]) with |dx|<=8?
    const int dgx = xi0 - xj0;           // dx for r=0,k=0; dx = dgx + r - k
    const bool xhit = (dgx >= -11) && (dgx <= 11);

    if (dy < -8 || dy > 8 || !xhit) {
        const float4 z = make_float4(0.f, 0.f, 0.f, 0.f);
        p[0] = z; p[ROWQ] = z; p[2 * ROWQ] = z; p[3 * ROWQ] = z;
        return;
    }

    const float sy = (float)(dy * dy);
    const float4* __restrict__ fb = g_feats + b * NPIX;
    // fj for the 4 columns this thread owns (shared across all 4 rows)
    float4 fj0 = fb[yj * WS + xj0];
    float4 fj1 = fb[yj * WS + xj0 + 1];
    float4 fj2 = fb[yj * WS + xj0 + 2];
    float4 fj3 = fb[yj * WS + xj0 + 3];

#pragma unroll
    for (int r = 0; r < 4; r++) {
        const int xi = xi0 + r;
        const float4 fi = fb[yi * WS + xi];   // uniform across CTA -> broadcast
        float res[4];
        const float4 fjs[4] = {fj0, fj1, fj2, fj3};
#pragma unroll
        for (int k = 0; k < 4; k++) {
            const int dx = xi - (xj0 + k);
            float val = 0.0f;
            if (dx >= -8 && dx <= 8) {
                const float4 fj = fjs[k];
                const float d0 = fi.x - fj.x;
                const float d1 = fi.y - fj.y;
                const float d2c = fi.z - fj.z;
                const float d2 = d0 * d0 + d1 * d1 + d2c * d2c;
                const float fdx = (float)dx;
                // exp(-(dy^2+dx^2)/50) * exp(-d2/0.02)
                const float E = fmaf(sy + fdx * fdx, -0.02f, -50.0f * d2);
                val = __expf(E);
            }
            res[k] = val;
        }
        p[r * ROWQ] = make_float4(res[0], res[1], res[2], res[3]);
    }
}

extern "C" void kernel_launch(void* const* d_in, const int* in_sizes, int n_in,
                              void* d_out, int out_size) {
    const float* img = (const float*)d_in[0];
    feats_kernel<<<(NB * NPIX + 255) / 256, 256>>>(img);
    dim3 grid(WS / 4, HS, NB);
    dim3 block(WS / 4, HS);
    affinity_kernel<<<grid, block>>>((float4*)d_out);
}

// round 3
// speedup vs baseline: 1.2969x; 1.0811x over previous
#include <cuda_runtime.h>

#define NB 16
#define H 768
#define W 768
#define HS 48
#define WS 48
#define NPIX (HS * WS)   // 2304
#define ROWQ (NPIX / 4)  // 576 float4 per output row
#define RAD 8

// scratch feats, padded to float4: [B][N] (w unused)
__device__ float4 g_feats[NB * NPIX];

__global__ void feats_kernel(const float* __restrict__ img) {
    int idx = blockIdx.x * blockDim.x + threadIdx.x;
    if (idx >= NB * NPIX) return;
    int b = idx / NPIX;
    int p = idx % NPIX;
    int yi = p / WS, xi = p % WS;
    // half-pixel centers, scale 16: src coord = 16*i + 7.5 -> 0.25 * (2x2 quad)
    int r0 = yi * 16 + 7;
    int c0 = xi * 16 + 7;
    float v[3];
#pragma unroll
    for (int c = 0; c < 3; c++) {
        const float* base = img + ((size_t)(b * 3 + c)) * H * W;
        float a = base[(size_t)r0 * W + c0] + base[(size_t)r0 * W + c0 + 1] +
                  base[(size_t)(r0 + 1) * W + c0] + base[(size_t)(r0 + 1) * W + c0 + 1];
        v[c] = 0.25f * a;
    }
    g_feats[idx] = make_float4(v[0], v[1], v[2], 0.0f);
}

// grid (3, 48, 16): x = role (0,1 = zero-fill halves, 2 = band compute),
// y = yi, z = b. 256 threads per CTA.
// For row block (b, yi): nonzero columns are the contiguous span
// [y0*48, (y1+1)*48) with y0 = max(0,yi-8), y1 = min(47,yi+8).
__global__ __launch_bounds__(256) void affinity_kernel(float4* __restrict__ out) {
    const int yi = blockIdx.y;
    const int b  = blockIdx.z;
    const int y0 = (yi - RAD > 0) ? yi - RAD : 0;
    const int y1 = (yi + RAD < HS - 1) ? yi + RAD : HS - 1;
    float4* const orow = out + (size_t)((b * HS + yi) * WS) * ROWQ;

    if (blockIdx.x < 2) {
        // ---- zero streamer: prefix [0, pq) and suffix [(y1+1)*12, 576) ----
        const int pq = y0 * 12;                       // prefix float4 per row
        const int zq = pq + (HS - 1 - y1) * 12;       // total zero float4 per row
        const int z = blockIdx.x * 256 + threadIdx.x;
        if (z >= zq) return;
        const int q = (z < pq) ? z : (y1 + 1) * 12 + (z - pq);
        float4* p = orow + q;
        const float4 zero = make_float4(0.f, 0.f, 0.f, 0.f);
#pragma unroll
        for (int r = 0; r < HS; r++) p[r * ROWQ] = zero;
        return;
    }

    // ---- band worker: thread owns (yj = y0 + tid/12, xj group = tid%12) ----
    const int wsize = y1 - y0 + 1;                    // 9..17
    const int yjo = threadIdx.x / 12;
    const int xj4 = threadIdx.x - yjo * 12;
    if (yjo >= wsize) return;
    const int yj = y0 + yjo;
    const int dy = yi - yj;
    const float sy = (float)(dy * dy);

    const float4* __restrict__ fb = g_feats + b * NPIX;
    const int xj0 = xj4 << 2;
    const float4 fj0 = fb[yj * WS + xj0];
    const float4 fj1 = fb[yj * WS + xj0 + 1];
    const float4 fj2 = fb[yj * WS + xj0 + 2];
    const float4 fj3 = fb[yj * WS + xj0 + 3];

    float4* p = orow + (yj * 12 + xj4);

#pragma unroll 8
    for (int xi = 0; xi < WS; xi++) {
        const float4 fi = fb[yi * WS + xi];           // uniform -> broadcast
        const int dxx = xi - xj0;
        float res[4];
        const float4 fjs[4] = {fj0, fj1, fj2, fj3};
#pragma unroll
        for (int k = 0; k < 4; k++) {
            const int dx = dxx - k;
            const float4 fj = fjs[k];
            const float d0 = fi.x - fj.x;
            const float d1 = fi.y - fj.y;
            const float d2c = fi.z - fj.z;
            const float d2 = d0 * d0 + d1 * d1 + d2c * d2c;
            const float fdx = (float)dx;
            // exp(-(dy^2+dx^2)/50) * exp(-d2/0.02)
            const float E = fmaf(sy + fdx * fdx, -0.02f, -50.0f * d2);
            res[k] = (dx >= -RAD && dx <= RAD) ? __expf(E) : 0.0f;
        }
        p[(size_t)xi * ROWQ] = make_float4(res[0], res[1], res[2], res[3]);
    }
}

extern "C" void kernel_launch(void* const* d_in, const int* in_sizes, int n_in,
                              void* d_out, int out_size) {
    const float* img = (const float*)d_in[0];
    feats_kernel<<<(NB * NPIX + 255) / 256, 256>>>(img);
    dim3 grid(3, HS, NB);
    affinity_kernel<<<grid, 256>>>((float4*)d_out);
}

// round 4
// speedup vs baseline: 1.4010x; 1.0803x over previous
#include <cuda_runtime.h>

#define NB 16
#define H 768
#define W 768
#define HS 48
#define WS 48
#define NPIX (HS * WS)   // 2304
#define ROWQ (NPIX / 4)  // 576 float4 per output row
#define RAD 8

// exp-related constants with log2(e) pre-folded (val = ex2(E))
#define CF_DY  (-0.02885390081777927f)   // -0.02 * log2(e)  (spatial term)
#define CF_SQ  (-72.13475204444817f)     // -50   * log2(e)  (|f|^2 terms)
#define CF_DOT (144.26950408889634f)     // +100  * log2(e)  (dot term)

__device__ float4 g_feats[NB * NPIX];

__device__ __forceinline__ float ex2f(float x) {
    float r;
    asm("ex2.approx.ftz.f32 %0, %1;" : "=f"(r) : "f"(x));
    return r;
}

// one thread per (b, channel, pixel): t = (b*3+c)*NPIX + p. 432 CTAs.
__global__ void feats_kernel(const float* __restrict__ img) {
    int t = blockIdx.x * 256 + threadIdx.x;      // 0 .. 110591
    int cb = t / NPIX;                           // = b*3 + c
    int p  = t - cb * NPIX;
    int b  = cb / 3;
    int c  = cb - b * 3;
    int yi = p / WS, xi = p - yi * WS;
    // bilinear 16x downsample, half-pixel centers -> mean of 2x2 quad
    int r0 = yi * 16 + 7;
    int c0 = xi * 16 + 7;
    const float* base = img + (size_t)cb * (H * W) + (size_t)r0 * W + c0;
    float v = 0.25f * (base[0] + base[1] + base[W] + base[W + 1]);
    ((float*)g_feats)[((size_t)(b * NPIX + p)) * 4 + c] = v;
}

// grid (6, 48, 16): x = role (0,1 zero-fill halves; 2..5 band xi-quarters),
// y = yi, z = b. 256 threads.
// Nonzero band for row block (b,yi): columns [y0*48, (y1+1)*48).
__global__ __launch_bounds__(256, 6) void affinity_kernel(float4* __restrict__ out) {
    const int yi = blockIdx.y;
    const int b  = blockIdx.z;
    const int y0 = (yi - RAD > 0) ? yi - RAD : 0;
    const int y1 = (yi + RAD < HS - 1) ? yi + RAD : HS - 1;
    float4* const orow = out + (size_t)((b * HS + yi) * WS) * ROWQ;
    const int role = blockIdx.x;

    if (role < 2) {
        // ---- zero streamer: prefix [0,pq) + suffix [(y1+1)*12, 576) ----
        const int pq = y0 * 12;
        const int zq = pq + (HS - 1 - y1) * 12;
        const int z = role * 256 + threadIdx.x;
        if (z >= zq) return;
        const int q = (z < pq) ? z : (y1 + 1) * 12 + (z - pq);
        float4* p = orow + q;
        const float4 zero = make_float4(0.f, 0.f, 0.f, 0.f);
#pragma unroll
        for (int r = 0; r < HS; r++) p[(size_t)r * ROWQ] = zero;
        return;
    }

    // ---- band worker: owns (yj, xj group), xi quarter [xib, xib+12) ----
    const int wsize = y1 - y0 + 1;               // 9..17
    const int yjo = threadIdx.x / 12;
    const int xj4 = threadIdx.x - yjo * 12;
    if (yjo >= wsize) return;
    const int yj = y0 + yjo;
    const int dy = yi - yj;
    const int xib = (role - 2) * 12;

    const float4* __restrict__ fb = g_feats + b * NPIX;
    const int xj0 = xj4 << 2;
    const float4 fj0 = fb[yj * WS + xj0];
    const float4 fj1 = fb[yj * WS + xj0 + 1];
    const float4 fj2 = fb[yj * WS + xj0 + 2];
    const float4 fj3 = fb[yj * WS + xj0 + 3];

    // per-thread hoisted: t_k = CF_DY*dy^2 + CF_SQ*|fj_k|^2 ; fjs_k = CF_DOT*fj_k
    const float dyt = CF_DY * (float)(dy * dy);
    const float t0 = fmaf(CF_SQ, fj0.x * fj0.x + fj0.y * fj0.y + fj0.z * fj0.z, dyt);
    const float t1 = fmaf(CF_SQ, fj1.x * fj1.x + fj1.y * fj1.y + fj1.z * fj1.z, dyt);
    const float t2 = fmaf(CF_SQ, fj2.x * fj2.x + fj2.y * fj2.y + fj2.z * fj2.z, dyt);
    const float t3 = fmaf(CF_SQ, fj3.x * fj3.x + fj3.y * fj3.y + fj3.z * fj3.z, dyt);
    const float3 s0 = make_float3(CF_DOT * fj0.x, CF_DOT * fj0.y, CF_DOT * fj0.z);
    const float3 s1 = make_float3(CF_DOT * fj1.x, CF_DOT * fj1.y, CF_DOT * fj1.z);
    const float3 s2 = make_float3(CF_DOT * fj2.x, CF_DOT * fj2.y, CF_DOT * fj2.z);
    const float3 s3 = make_float3(CF_DOT * fj3.x, CF_DOT * fj3.y, CF_DOT * fj3.z);

    float4* p = orow + (size_t)xib * ROWQ + (y0 * 12 + threadIdx.x);

#pragma unroll 4
    for (int ii = 0; ii < 12; ii++) {
        const int xi = xib + ii;
        const float4 fi = fb[yi * WS + xi];              // CTA-uniform -> broadcast
        const float si = CF_SQ * (fi.x * fi.x + fi.y * fi.y + fi.z * fi.z);
        const float fdx0 = (float)(xi - xj0);
        float res[4];
        {
            const float3 ss[4] = {s0, s1, s2, s3};
            const float tt[4] = {t0, t1, t2, t3};
#pragma unroll
            for (int k = 0; k < 4; k++) {
                const float dxk = fdx0 - (float)k;
                float e = fmaf(CF_DY * dxk, dxk, tt[k] + si);
                e = fmaf(fi.x, ss[k].x, e);
                e = fmaf(fi.y, ss[k].y, e);
                e = fmaf(fi.z, ss[k].z, e);
                const float v = ex2f(e);
                res[k] = (fabsf(dxk) <= 8.0f) ? v : 0.0f;
            }
        }
        p[(size_t)ii * ROWQ] = make_float4(res[0], res[1], res[2], res[3]);
    }
}

extern "C" void kernel_launch(void* const* d_in, const int* in_sizes, int n_in,
                              void* d_out, int out_size) {
    const float* img = (const float*)d_in[0];
    feats_kernel<<<(NB * NPIX * 3) / 256, 256>>>(img);
    dim3 grid(6, HS, NB);
    affinity_kernel<<<grid, 256>>>((float4*)d_out);
}